// round 1
// baseline (speedup 1.0000x reference)
#include <cuda_runtime.h>

#define B_DIM 4
#define C_DIM 2
#define E_DIM 256
#define L_DIM 16000
#define W_DIM 40
#define STEP  20
#define T_DIM ((L_DIM - 1) * STEP + W_DIM)   // 320020
#define NT    512

// ---------- packed f32x2 helpers ----------
__device__ __forceinline__ unsigned long long pack2(float lo, float hi) {
    unsigned long long r;
    asm("mov.b64 %0, {%1, %2};" : "=l"(r) : "f"(lo), "f"(hi));
    return r;
}
__device__ __forceinline__ void unpack2(unsigned long long v, float& lo, float& hi) {
    asm("mov.b64 {%0, %1}, %2;" : "=f"(lo), "=f"(hi) : "l"(v));
}
__device__ __forceinline__ void fma2(unsigned long long& acc,
                                     unsigned long long a, unsigned long long b) {
    asm("fma.rn.f32x2 %0, %1, %2, %0;" : "+l"(acc) : "l"(a), "l"(b));
}

// ---------- zero-init (d_out is poisoned; atomic targets need 0) ----------
__global__ void zero_kernel(float4* __restrict__ out, int n4) {
    int i = blockIdx.x * blockDim.x + threadIdx.x;
    if (i < n4) out[i] = make_float4(0.f, 0.f, 0.f, 0.f);
}

// ---------- fused overlap-add epilogue for one channel ----------
__device__ __forceinline__ void write_out(float* __restrict__ out, size_t base,
                                          const unsigned long long* acc,
                                          int lane, int l) {
    float f[W_DIM];
#pragma unroll
    for (int q = 0; q < 20; ++q) unpack2(acc[q], f[2 * q], f[2 * q + 1]);

    // segment l = frame[l][0:20] + frame[l-1][20:40] (from lane-1 via shuffle)
#pragma unroll
    for (int j = 0; j < STEP; ++j) {
        float up = __shfl_up_sync(0xffffffffu, f[STEP + j], 1);
        float lo = f[j];
        if (lane > 0)      out[base + j] = lo + up;          // complete value
        else if (l > 0)    atomicAdd(&out[base + j], lo);    // pair arrives from prev warp
        else               out[base + j] = lo;               // l==0: sole contributor
    }
    // lane 31's upper half belongs to the next warp's leading segment
    if (lane == 31) {
#pragma unroll
        for (int j = 0; j < STEP; ++j)
            atomicAdd(&out[base + STEP + j], f[STEP + j]);
    }
}

__global__ void __launch_bounds__(NT, 1)
decoder_kernel(const float* __restrict__ mix,
               const float* __restrict__ mask,
               const float* __restrict__ basis,
               float* __restrict__ out) {
    // basis transposed into shared: bsh[e][w], rows of 40 floats (160B, 16B-aligned)
    __shared__ float bsh[E_DIM * W_DIM];
    for (int i = threadIdx.x; i < E_DIM * W_DIM; i += NT) {
        int e = i / W_DIM, w = i - e * W_DIM;
        bsh[i] = basis[w * E_DIM + e];
    }
    __syncthreads();

    const int item = blockIdx.x * NT + threadIdx.x;   // exactly B*L items
    const int b = item / L_DIM;
    const int l = item - b * L_DIM;
    const int lane = threadIdx.x & 31;

    const float* pm  = mix  + (size_t)b * E_DIM * L_DIM + l;
    const float* pk0 = mask + ((size_t)b * C_DIM + 0) * E_DIM * L_DIM + l;
    const float* pk1 = pk0 + (size_t)E_DIM * L_DIM;

    unsigned long long acc0[20], acc1[20];
#pragma unroll
    for (int i = 0; i < 20; ++i) { acc0[i] = 0ull; acc1[i] = 0ull; }

#pragma unroll 1
    for (int e = 0; e < E_DIM; ++e) {
        float m  = __ldg(pm);
        float s0 = m * __ldg(pk0);
        float s1 = m * __ldg(pk1);
        pm += L_DIM; pk0 += L_DIM; pk1 += L_DIM;

        unsigned long long s0d = pack2(s0, s0);
        unsigned long long s1d = pack2(s1, s1);

        const float4* brow = reinterpret_cast<const float4*>(&bsh[e * W_DIM]);
#pragma unroll
        for (int q = 0; q < 10; ++q) {
            float4 bv = brow[q];                 // LDS.128 broadcast (uniform addr)
            unsigned long long p0 = pack2(bv.x, bv.y);
            unsigned long long p1 = pack2(bv.z, bv.w);
            fma2(acc0[2 * q],     s0d, p0);
            fma2(acc0[2 * q + 1], s0d, p1);
            fma2(acc1[2 * q],     s1d, p0);
            fma2(acc1[2 * q + 1], s1d, p1);
        }
    }

    const size_t base0 = ((size_t)b * C_DIM + 0) * T_DIM + (size_t)l * STEP;
    const size_t base1 = base0 + T_DIM;
    write_out(out, base0, acc0, lane, l);
    write_out(out, base1, acc1, lane, l);
}

extern "C" void kernel_launch(void* const* d_in, const int* in_sizes, int n_in,
                              void* d_out, int out_size) {
    // Identify inputs by element count for robustness.
    const float *mix = nullptr, *mask = nullptr, *basis = nullptr;
    for (int i = 0; i < n_in; ++i) {
        long long s = in_sizes[i];
        if (s == (long long)B_DIM * E_DIM * L_DIM)              mix   = (const float*)d_in[i];
        else if (s == (long long)B_DIM * C_DIM * E_DIM * L_DIM) mask  = (const float*)d_in[i];
        else if (s == (long long)W_DIM * E_DIM)                 basis = (const float*)d_in[i];
    }
    float* out = (float*)d_out;

    int n4 = out_size / 4;
    zero_kernel<<<(n4 + 255) / 256, 256>>>((float4*)out, n4);

    decoder_kernel<<<(B_DIM * L_DIM) / NT, NT>>>(mix, mask, basis, out);
}

// round 2
// speedup vs baseline: 1.6269x; 1.6269x over previous
#include <cuda_runtime.h>

#define B_DIM 4
#define C_DIM 2
#define E_DIM 256
#define L_DIM 16000
#define W_DIM 40
#define STEP  20
#define T_DIM ((L_DIM - 1) * STEP + W_DIM)   // 320020
#define NT    128
#define EUNR  4

// ---------- packed f32x2 helpers ----------
__device__ __forceinline__ unsigned long long pack2(float lo, float hi) {
    unsigned long long r;
    asm("mov.b64 %0, {%1, %2};" : "=l"(r) : "f"(lo), "f"(hi));
    return r;
}
__device__ __forceinline__ void unpack2(unsigned long long v, float& lo, float& hi) {
    asm("mov.b64 {%0, %1}, %2;" : "=f"(lo), "=f"(hi) : "l"(v));
}
__device__ __forceinline__ void fma2(unsigned long long& acc,
                                     unsigned long long a, unsigned long long b) {
    asm("fma.rn.f32x2 %0, %1, %2, %0;" : "+l"(acc) : "l"(a), "l"(b));
}

// ---------- zero-init (d_out is poisoned; atomic targets need 0) ----------
__global__ void zero_kernel(float4* __restrict__ out, int n4) {
    int i = blockIdx.x * blockDim.x + threadIdx.x;
    if (i < n4) out[i] = make_float4(0.f, 0.f, 0.f, 0.f);
}

// ---------- fused overlap-add epilogue for one channel ----------
__device__ __forceinline__ void write_out(float* __restrict__ out, size_t base,
                                          const unsigned long long* acc,
                                          int lane, int l) {
    float f[W_DIM];
#pragma unroll
    for (int q = 0; q < 20; ++q) unpack2(acc[q], f[2 * q], f[2 * q + 1]);

    // segment l = frame[l][0:20] + frame[l-1][20:40] (from lane-1 via shuffle)
#pragma unroll
    for (int j = 0; j < STEP; ++j) {
        float up = __shfl_up_sync(0xffffffffu, f[STEP + j], 1);
        float lo = f[j];
        if (lane > 0)      out[base + j] = lo + up;          // complete value
        else if (l > 0)    atomicAdd(&out[base + j], lo);    // pair arrives from prev warp
        else               out[base + j] = lo;               // l==0: sole contributor
    }
    // lane 31's upper half belongs to the next warp's leading segment
    if (lane == 31) {
#pragma unroll
        for (int j = 0; j < STEP; ++j)
            atomicAdd(&out[base + STEP + j], f[STEP + j]);
    }
}

__global__ void __launch_bounds__(NT, 4)
decoder_kernel(const float* __restrict__ mix,
               const float* __restrict__ mask,
               const float* __restrict__ basis,
               float* __restrict__ out) {
    // basis transposed into shared: bsh[e][w], rows of 40 floats (160B, 16B-aligned)
    __shared__ float bsh[E_DIM * W_DIM];
    for (int i = threadIdx.x; i < E_DIM * W_DIM; i += NT) {
        int e = i / W_DIM, w = i - e * W_DIM;
        bsh[i] = basis[w * E_DIM + e];
    }
    __syncthreads();

    const int item = blockIdx.x * NT + threadIdx.x;   // exactly B*L items
    const int b = item / L_DIM;
    const int l = item - b * L_DIM;
    const int lane = threadIdx.x & 31;

    const float* pm  = mix  + (size_t)b * E_DIM * L_DIM + l;
    const float* pk0 = mask + ((size_t)b * C_DIM + 0) * E_DIM * L_DIM + l;
    const float* pk1 = pk0 + (size_t)E_DIM * L_DIM;

    unsigned long long acc0[20], acc1[20];
#pragma unroll
    for (int i = 0; i < 20; ++i) { acc0[i] = 0ull; acc1[i] = 0ull; }

#pragma unroll 1
    for (int e = 0; e < E_DIM; e += EUNR) {
        // front-batched loads: 12 independent LDGs in flight (MLP=12)
        float m[EUNR], kv0[EUNR], kv1[EUNR];
#pragma unroll
        for (int u = 0; u < EUNR; ++u) m[u]   = __ldg(pm  + (size_t)u * L_DIM);
#pragma unroll
        for (int u = 0; u < EUNR; ++u) kv0[u] = __ldg(pk0 + (size_t)u * L_DIM);
#pragma unroll
        for (int u = 0; u < EUNR; ++u) kv1[u] = __ldg(pk1 + (size_t)u * L_DIM);
        pm  += (size_t)EUNR * L_DIM;
        pk0 += (size_t)EUNR * L_DIM;
        pk1 += (size_t)EUNR * L_DIM;

#pragma unroll
        for (int u = 0; u < EUNR; ++u) {
            float s0 = m[u] * kv0[u];
            float s1 = m[u] * kv1[u];
            unsigned long long s0d = pack2(s0, s0);
            unsigned long long s1d = pack2(s1, s1);

            // basis row already packed as f32x2 pairs in shared (uniform addr -> broadcast)
            const unsigned long long* brow =
                reinterpret_cast<const unsigned long long*>(&bsh[(e + u) * W_DIM]);
#pragma unroll
            for (int q = 0; q < 20; ++q) {
                fma2(acc0[q], s0d, brow[q]);
                fma2(acc1[q], s1d, brow[q]);
            }
        }
    }

    const size_t base0 = ((size_t)b * C_DIM + 0) * T_DIM + (size_t)l * STEP;
    const size_t base1 = base0 + T_DIM;
    write_out(out, base0, acc0, lane, l);
    write_out(out, base1, acc1, lane, l);
}

extern "C" void kernel_launch(void* const* d_in, const int* in_sizes, int n_in,
                              void* d_out, int out_size) {
    // Identify inputs by element count for robustness.
    const float *mix = nullptr, *mask = nullptr, *basis = nullptr;
    for (int i = 0; i < n_in; ++i) {
        long long s = in_sizes[i];
        if (s == (long long)B_DIM * E_DIM * L_DIM)              mix   = (const float*)d_in[i];
        else if (s == (long long)B_DIM * C_DIM * E_DIM * L_DIM) mask  = (const float*)d_in[i];
        else if (s == (long long)W_DIM * E_DIM)                 basis = (const float*)d_in[i];
    }
    float* out = (float*)d_out;

    int n4 = out_size / 4;
    zero_kernel<<<(n4 + 255) / 256, 256>>>((float4*)out, n4);

    decoder_kernel<<<(B_DIM * L_DIM) / NT, NT>>>(mix, mask, basis, out);
}